// round 8
// baseline (speedup 1.0000x reference)
#include <cuda_runtime.h>
#include <cuda_fp16.h>
#include <cstdint>
#include <math.h>

#define T_STEPS 1000
#define I_DIM   100
#define H_DIM   5000
#define H4      (H_DIM/4)            // 1250 float4 per fp32 row
#define O_DIM   100
#define ALPHA_F 0.1f
#define NOISE_F 0.1f

#define NBLK   148       // persistent grid: one CTA per SM
#define NTH    512
#define NWARP  (NTH/32)
#define MAXR   34        // max rows per CTA

#define NC        5      // column chunks per step (5000 = 5 * 1000)
#define CU4       125    // uint4 (8 halves) per row per chunk
#define STAGES    3
#define BLOCK_U4  (MAXR * CU4)                 // 4250 uint4 = 68000 B
#define STAGE_U4  BLOCK_U4
#define TOTCHUNK  (T_STEPS * NC)
#define DYN_BYTES (STAGES*STAGE_U4*16 + H4*16)          // 224000 B

__device__ float    g_inj[(size_t)T_STEPS * H_DIM];
__device__ uint4    g_wh4[(size_t)NBLK * NC * BLOCK_U4];   // fp16 W, CTA/chunk-blocked
__device__ unsigned g_bar;

__global__ void reset_k() { g_bar = 0u; }

// ---------------------------------------------------------------------------
// Convert + reorganize W_rec fp32 -> fp16 into per-(CTA, chunk) contiguous
// blocks of MAXR rows x 1000 cols (row lr at block + lr*2000 B).
// ---------------------------------------------------------------------------
__global__ void cvt_k(const float* __restrict__ W) {
    const size_t total = (size_t)NBLK * NC * MAXR * CU4;
    const size_t idx = (size_t)blockIdx.x * blockDim.x + threadIdx.x;
    if (idx >= total) return;
    const int    j  = (int)(idx % CU4);
    const size_t r1 = idx / CU4;
    const int    lr = (int)(r1 % MAXR);
    const size_t r2 = r1 / MAXR;
    const int    c  = (int)(r2 % NC);
    const int    b  = (int)(r2 / NC);

    const int row0  = (int)(((long long)b     * H_DIM) / NBLK);
    const int nrows = (int)(((long long)(b+1) * H_DIM) / NBLK) - row0;
    if (lr >= nrows) return;

    const float4* s = reinterpret_cast<const float4*>(W)
                    + (size_t)(row0 + lr) * H4 + c * (CU4 * 2) + 2 * j;
    const float4 a = __ldcs(s);
    const float4 bb = __ldcs(s + 1);
    uint4 o;
    __half2* p = reinterpret_cast<__half2*>(&o);
    p[0] = __floats2half2_rn(a.x,  a.y);
    p[1] = __floats2half2_rn(a.z,  a.w);
    p[2] = __floats2half2_rn(bb.x, bb.y);
    p[3] = __floats2half2_rn(bb.z, bb.w);
    g_wh4[idx] = o;
}

// ---------------------------------------------------------------------------
// inj[t][h] = sum_i u[t][i] * W_in[h][i] + 0.1 * noise[t][h]
// ---------------------------------------------------------------------------
__global__ void inj_k(const float* __restrict__ u,
                      const float* __restrict__ noise,
                      const float* __restrict__ W_in) {
    __shared__ float u_s[I_DIM];
    const int t   = blockIdx.y;
    const int tid = threadIdx.x;
    if (tid < I_DIM) u_s[tid] = u[(size_t)t * I_DIM + tid];
    __syncthreads();

    const int h = blockIdx.x * blockDim.x + tid;
    if (h < H_DIM) {
        const float4* w4 = reinterpret_cast<const float4*>(W_in + (size_t)h * I_DIM);
        float acc = 0.0f;
#pragma unroll
        for (int i = 0; i < I_DIM / 4; i++) {
            float4 w = __ldg(&w4[i]);
            acc = fmaf(w.x, u_s[4*i+0], acc);
            acc = fmaf(w.y, u_s[4*i+1], acc);
            acc = fmaf(w.z, u_s[4*i+2], acc);
            acc = fmaf(w.w, u_s[4*i+3], acc);
        }
        g_inj[(size_t)t * H_DIM + h] = acc + NOISE_F * noise[(size_t)t * H_DIM + h];
    }
}

// ---------------------------------------------------------------------------
// mbarrier helpers
// ---------------------------------------------------------------------------
__device__ __forceinline__ void mbar_init(unsigned addr, unsigned count) {
    asm volatile("mbarrier.init.shared.b64 [%0], %1;" :: "r"(addr), "r"(count) : "memory");
}
__device__ __forceinline__ void mbar_expect_tx(unsigned addr, unsigned bytes) {
    asm volatile("mbarrier.arrive.expect_tx.shared.b64 _, [%0], %1;"
                 :: "r"(addr), "r"(bytes) : "memory");
}
__device__ __forceinline__ void mbar_wait(unsigned addr, unsigned parity) {
    asm volatile(
        "{\n\t.reg .pred P1;\n\t"
        "W_%=:\n\t"
        "mbarrier.try_wait.parity.acquire.cta.shared::cta.b64 P1, [%0], %1, 0x989680;\n\t"
        "@P1 bra D_%=;\n\t"
        "bra W_%=;\n\t"
        "D_%=:\n\t}"
        :: "r"(addr), "r"(parity) : "memory");
}
__device__ __forceinline__ void tma_1d(unsigned dst, const void* src,
                                       unsigned bytes, unsigned mbar) {
    asm volatile(
        "cp.async.bulk.shared::cta.global.mbarrier::complete_tx::bytes [%0], [%1], %2, [%3];"
        :: "r"(dst), "l"(src), "r"(bytes), "r"(mbar) : "memory");
}

// ---------------------------------------------------------------------------
// fp16 weights * fp32 r, fp32 accumulate (8 cols per uint4)
// ---------------------------------------------------------------------------
__device__ __forceinline__ void fma8(float4& a, const uint4 wv,
                                     const float4 rA, const float4 rB) {
    const __half2* h = reinterpret_cast<const __half2*>(&wv);
    const float2 f0 = __half22float2(h[0]);
    const float2 f1 = __half22float2(h[1]);
    const float2 f2 = __half22float2(h[2]);
    const float2 f3 = __half22float2(h[3]);
    a.x = fmaf(f0.x, rA.x, a.x); a.y = fmaf(f0.y, rA.y, a.y);
    a.z = fmaf(f1.x, rA.z, a.z); a.w = fmaf(f1.y, rA.w, a.w);
    a.x = fmaf(f2.x, rB.x, a.x); a.y = fmaf(f2.y, rB.y, a.y);
    a.z = fmaf(f3.x, rB.z, a.z); a.w = fmaf(f3.y, rB.w, a.w);
}

// ---------------------------------------------------------------------------
// Persistent scan. Chunk k = t*NC + c lives in smem stage k % 3; one TMA
// bulk copy per chunk, mbarrier completion, one __syncthreads per chunk
// (WAR protection for stage reuse). Waiter parity = (k/3) & 1.
// ---------------------------------------------------------------------------
__global__ void __launch_bounds__(NTH, 1)
scan_k(const float* __restrict__ r_in,
       float* __restrict__ hs) {
    extern __shared__ uint4 dynu[];
    uint4*  wbuf = dynu;                                   // [STAGES][BLOCK_U4]
    float4* r4   = reinterpret_cast<float4*>(dynu + STAGES * STAGE_U4);  // 1250
    __shared__ float x_s[MAXR];
    __shared__ __align__(8) unsigned long long mbar_s[STAGES];

    const int tid  = threadIdx.x;
    const int bid  = blockIdx.x;
    const int wid  = tid >> 5;
    const int lane = tid & 31;

    const int row0  = (int)(((long long)bid     * H_DIM) / NBLK);
    const int row1  = (int)(((long long)(bid+1) * H_DIM) / NBLK);
    const int nrows = row1 - row0;                         // 33 or 34

    const int lr0 = wid;
    const int lr1 = wid + NWARP;
    const int lr2 = wid + 2 * NWARP;
    const bool has2 = (lr2 < nrows);

    const unsigned mbA0 = (unsigned)__cvta_generic_to_shared(&mbar_s[0]);
    const unsigned mbA1 = (unsigned)__cvta_generic_to_shared(&mbar_s[1]);
    const unsigned mbA2 = (unsigned)__cvta_generic_to_shared(&mbar_s[2]);
    auto mb_of = [&](int s) { return s == 0 ? mbA0 : (s == 1 ? mbA1 : mbA2); };

    if (tid < nrows) {
        float rv = r_in[row0 + tid];
        hs[row0 + tid] = rv;                               // hidden_states[0]
        x_s[tid] = atanhf(rv);
    }
    if (tid == 0) {
        mbar_init(mbA0, 1); mbar_init(mbA1, 1); mbar_init(mbA2, 1);
    }
    __syncthreads();

    const uint4* gbase = g_wh4 + (size_t)bid * NC * BLOCK_U4;
    const unsigned nbytes = (unsigned)(nrows * 2000);      // bytes per chunk block

    auto issue = [&](int cc, int s) {                      // tid 0 only
        const unsigned mb  = mb_of(s);
        const unsigned dst = (unsigned)__cvta_generic_to_shared(wbuf + s * STAGE_U4);
        mbar_expect_tx(mb, nbytes);
        tma_1d(dst, gbase + (size_t)cc * BLOCK_U4, nbytes, mb);
    };

    if (tid == 0) { issue(0, 0); issue(1, 1); }            // prologue: k=0,1
    int stage = 0, n3 = 0;                                 // consume ptr: k%3, k/3
    int nstage = 2, nchunk = 2;                            // issue slot (k+2)
    int kissued = 2;

    for (int t = 0; t < T_STEPS; t++) {
        // Stage r_t into shared (visibility via the c=0 __syncthreads below).
        const float4* rsrc = (t == 0)
            ? reinterpret_cast<const float4*>(r_in)
            : reinterpret_cast<const float4*>(hs + (size_t)t * H_DIM);
        for (int i = tid; i < H4; i += NTH) r4[i] = __ldcg(rsrc + i);

        float4 a0 = make_float4(0.f,0.f,0.f,0.f);
        float4 a1 = make_float4(0.f,0.f,0.f,0.f);
        float4 a2 = make_float4(0.f,0.f,0.f,0.f);

        for (int c = 0; c < NC; c++) {
            mbar_wait(mb_of(stage), (unsigned)(n3 & 1));   // chunk k data ready
            __syncthreads();                               // all past chunk k-1

            if (tid == 0 && kissued < TOTCHUNK) issue(nchunk, nstage);
            kissued++;
            nstage = (nstage == 2) ? 0 : nstage + 1;
            nchunk = (nchunk == NC - 1) ? 0 : nchunk + 1;

            const uint4* wb = wbuf + stage * STAGE_U4;
            if (stage == 2) { stage = 0; n3++; } else stage++;

            const float4* rc = r4 + c * (CU4 * 2);         // 250 float4 per chunk
            const uint4* w0 = wb + lr0 * CU4;
            const uint4* w1 = wb + lr1 * CU4;
            const uint4* w2 = wb + lr2 * CU4;

#pragma unroll
            for (int it = 0; it < 4; it++) {
                const int col = lane + it * 32;
                if (it < 3 || lane < CU4 - 96) {
                    const float4 rA = rc[2*col];
                    const float4 rB = rc[2*col + 1];
                    fma8(a0, w0[col], rA, rB);
                    fma8(a1, w1[col], rA, rB);
                    if (has2) fma8(a2, w2[col], rA, rB);
                }
            }
        }

        // Reduce + state update for the warp's rows.
        float s0 = (a0.x + a0.y) + (a0.z + a0.w);
        float s1 = (a1.x + a1.y) + (a1.z + a1.w);
        float s2 = (a2.x + a2.y) + (a2.z + a2.w);
#pragma unroll
        for (int sh = 16; sh; sh >>= 1) {
            s0 += __shfl_down_sync(0xffffffffu, s0, sh);
            s1 += __shfl_down_sync(0xffffffffu, s1, sh);
            s2 += __shfl_down_sync(0xffffffffu, s2, sh);
        }
        if (lane == 0) {
            {   const int row = row0 + lr0;
                float x = (1.0f-ALPHA_F)*x_s[lr0]
                        + ALPHA_F*(s0 + __ldcg(&g_inj[(size_t)t*H_DIM + row]));
                x_s[lr0] = x;
                hs[(size_t)(t+1)*H_DIM + row] = tanhf(x); }
            {   const int row = row0 + lr1;
                float x = (1.0f-ALPHA_F)*x_s[lr1]
                        + ALPHA_F*(s1 + __ldcg(&g_inj[(size_t)t*H_DIM + row]));
                x_s[lr1] = x;
                hs[(size_t)(t+1)*H_DIM + row] = tanhf(x); }
            if (has2) {
                const int row = row0 + lr2;
                float x = (1.0f-ALPHA_F)*x_s[lr2]
                        + ALPHA_F*(s2 + __ldcg(&g_inj[(size_t)t*H_DIM + row]));
                x_s[lr2] = x;
                hs[(size_t)(t+1)*H_DIM + row] = tanhf(x); }
            __threadfence();                               // release stores
        }
        __syncthreads();

        // Grid barrier: atomic arrive + read-only poll.
        if (tid == 0) {
            atomicAdd(&g_bar, 1u);
            const unsigned target = (unsigned)(t + 1) * (unsigned)NBLK;
            while (*((volatile unsigned*)&g_bar) < target) { }
            __threadfence();                               // acquire
        }
        __syncthreads();
    }
}

// ---------------------------------------------------------------------------
// o[t][j] = sum_h hs[t+1][h] * W_out[j][h]
// ---------------------------------------------------------------------------
__global__ void out_k(const float* __restrict__ hs,
                      const float* __restrict__ W_out,
                      float* __restrict__ o) {
    __shared__ float r_s[H_DIM];
    const int t    = blockIdx.x;
    const int tid  = threadIdx.x;
    const int wid  = tid >> 5;
    const int lane = tid & 31;

    const float* r = hs + (size_t)(t + 1) * H_DIM;
    for (int c = tid; c < H_DIM; c += blockDim.x) r_s[c] = r[c];
    __syncthreads();

    for (int j = wid; j < O_DIM; j += blockDim.x / 32) {
        const float* wrow = W_out + (size_t)j * H_DIM;
        float acc = 0.0f;
        for (int c = lane; c < H_DIM; c += 32)
            acc = fmaf(__ldg(wrow + c), r_s[c], acc);
#pragma unroll
        for (int s = 16; s; s >>= 1) acc += __shfl_down_sync(0xffffffffu, acc, s);
        if (lane == 0) o[(size_t)t * O_DIM + j] = acc;
    }
}

// ---------------------------------------------------------------------------
// Inputs: u (T,I), r (H), noise (T,H), W_in (H,I), W_rec (H,H), W_out (O,H).
// Output: hidden_states (T+1,H) then o (T,O), fp32.
// ---------------------------------------------------------------------------
extern "C" void kernel_launch(void* const* d_in, const int* in_sizes, int n_in,
                              void* d_out, int out_size) {
    const float* u     = (const float*)d_in[0];
    const float* r     = (const float*)d_in[1];
    const float* noise = (const float*)d_in[2];
    const float* W_in  = (const float*)d_in[3];
    const float* W_rec = (const float*)d_in[4];
    const float* W_out = (const float*)d_in[5];

    float* hs = (float*)d_out;                       // (T+1, H)
    float* o  = hs + (size_t)(T_STEPS + 1) * H_DIM;  // (T, O)

    cudaFuncSetAttribute(scan_k, cudaFuncAttributeMaxDynamicSharedMemorySize,
                         DYN_BYTES);

    reset_k<<<1, 1>>>();
    dim3 gi((H_DIM + 255) / 256, T_STEPS);
    inj_k<<<gi, 256>>>(u, noise, W_in);
    const size_t cvt_total = (size_t)NBLK * NC * MAXR * CU4;
    cvt_k<<<(int)((cvt_total + 255) / 256), 256>>>(W_rec);
    scan_k<<<NBLK, NTH, DYN_BYTES>>>(r, hs);
    out_k<<<T_STEPS, 256>>>(hs, W_out, o);
}